// round 8
// baseline (speedup 1.0000x reference)
#include <cuda_runtime.h>
#include <cuda_bf16.h>

#define SDIM    4096
#define HDIM    16
#define PDIM    64
#define NDIM    64
#define LCHUNK  64
#define NCHUNK  64
#define NBH     128
#define THRESH  14.0f     // exp(-14)=8e-7; truncation ~1e-5 rel << 1e-3 budget
#define CAP     4         // chunk slots in smem
#define PRE0    (NCHUNK - CAP)   // 60: first speculatively prefetched chunk
#define THREADS 512
#define WIN     1024      // backward A-scan window

// Dynamic smem (floats):
//   xsd slots : [CAP][64][128]  scaled+duplicated X  (128KB)
//               (compact X staged in first 4096 floats of each slot pre-dup)
//   bs  slots : [CAP][64][64]   B tiles              (64KB)
//   ws        : [SDIM]          decay weights        (16KB)
#define XSD_STRIDE 128
#define XSD_SLOT   (LCHUNK * XSD_STRIDE)   // 8192 floats
#define BS_SLOT    (LCHUNK * NDIM)         // 4096 floats
#define XSD_OFF 0
#define BS_OFF  (CAP * XSD_SLOT)           // 32768
#define WS_OFF  (BS_OFF + CAP * BS_SLOT)   // 49152
#define SMEM_BYTES ((WS_OFF + SDIM) * 4)   // 212992 B

__device__ __forceinline__ void ffma2(unsigned long long& d,
                                      unsigned long long a,
                                      unsigned long long b) {
    asm("fma.rn.f32x2 %0, %1, %2, %0;" : "+l"(d) : "l"(a), "l"(b));
}
__device__ __forceinline__ void fadd2(unsigned long long& d, unsigned long long a) {
    asm("add.rn.f32x2 %0, %0, %1;" : "+l"(d) : "l"(a));
}
__device__ __forceinline__ void cp16(float* smem_dst, const float4* gmem_src) {
    unsigned sptr = (unsigned)__cvta_generic_to_shared(smem_dst);
    asm volatile("cp.async.cg.shared.global [%0], [%1], 16;"
                 :: "r"(sptr), "l"(gmem_src) : "memory");
}

union F4U2 { float4 f4; unsigned long long u2[2]; };

// Issue cp.async for one chunk: compact X into slot base, B into bs slot.
__device__ __forceinline__ void load_chunk(float* sm, int slot, int chunk,
                                           int b, int h, int tid,
                                           const float4* X4, const float4* B4) {
    const long tbase = (long)(b * SDIM + chunk * LCHUNK) * HDIM + h;
    float* xsl = sm + XSD_OFF + slot * XSD_SLOT;   // compact staging
    float* bsl = sm + BS_OFF  + slot * BS_SLOT;
    #pragma unroll
    for (int k = 0; k < 2; k++) {
        const int i   = k * THREADS + tid;   // 0..1023
        const int row = i >> 4;
        const int col = i & 15;
        const long g  = (tbase + (long)row * HDIM) * 16 + col;
        cp16(xsl + row * 64 + col * 4, X4 + g);
        cp16(bsl + row * 64 + col * 4, B4 + g);
    }
}

// Scale compact X by decay weight and expand in-place to duplicated layout.
// Contains one internal __syncthreads (read-before-overwrite). All threads.
__device__ __forceinline__ void scale_dup(float* sm, const float* ws,
                                          int slot, int chunk, int tid) {
    float* xsl = sm + XSD_OFF + slot * XSD_SLOT;
    float4 xv[2];
    int row[2], col[2];
    #pragma unroll
    for (int k = 0; k < 2; k++) {
        const int i = k * THREADS + tid;
        row[k] = i >> 4;
        col[k] = i & 15;
        xv[k] = *(const float4*)&xsl[row[k] * 64 + col[k] * 4];
    }
    __syncthreads();
    #pragma unroll
    for (int k = 0; k < 2; k++) {
        const float w = ws[chunk * LCHUNK + row[k]];
        float4 lo, hi;
        lo.x = xv[k].x * w; lo.y = lo.x;   // note: want (x0w,x0w,x1w,x1w)
        lo.y = xv[k].x * w;                // keep it explicit below instead
        lo.x = xv[k].x * w; lo.y = xv[k].x * w;
        lo.z = xv[k].y * w; lo.w = xv[k].y * w;
        hi.x = xv[k].z * w; hi.y = xv[k].z * w;
        hi.z = xv[k].w * w; hi.w = xv[k].w * w;
        float* dst = &xsl[row[k] * XSD_STRIDE + col[k] * 8];
        *(float4*)dst       = lo;
        *(float4*)(dst + 4) = hi;
    }
}

// Compute one chunk (this thread-group's half of l). 11 slots/iter.
__device__ __forceinline__ void compute_chunk(const float* sm, int slot,
                                              int lh, int p0, int n0,
                                              unsigned long long acc[4][2]) {
    const float* xsl = sm + XSD_OFF + slot * XSD_SLOT + lh * 32 * XSD_STRIDE;
    const float* bsl = sm + BS_OFF  + slot * BS_SLOT  + lh * 32 * NDIM;
    F4U2 xd0, xd1, bv;
    xd0.f4 = *(const float4*)&xsl[2 * p0];
    xd1.f4 = *(const float4*)&xsl[2 * p0 + 4];
    bv.f4  = *(const float4*)&bsl[n0];
    #pragma unroll 8
    for (int l = 0; l < 32; l++) {
        F4U2 nxd0, nxd1, nbv;
        if (l < 31) {
            nxd0.f4 = *(const float4*)&xsl[(l + 1) * XSD_STRIDE + 2 * p0];
            nxd1.f4 = *(const float4*)&xsl[(l + 1) * XSD_STRIDE + 2 * p0 + 4];
            nbv.f4  = *(const float4*)&bsl[(l + 1) * NDIM + n0];
        }
        ffma2(acc[0][0], xd0.u2[0], bv.u2[0]);
        ffma2(acc[0][1], xd0.u2[0], bv.u2[1]);
        ffma2(acc[1][0], xd0.u2[1], bv.u2[0]);
        ffma2(acc[1][1], xd0.u2[1], bv.u2[1]);
        ffma2(acc[2][0], xd1.u2[0], bv.u2[0]);
        ffma2(acc[2][1], xd1.u2[0], bv.u2[1]);
        ffma2(acc[3][0], xd1.u2[1], bv.u2[0]);
        ffma2(acc[3][1], xd1.u2[1], bv.u2[1]);
        xd0 = nxd0; xd1 = nxd1; bv = nbv;
    }
}

__global__ void __launch_bounds__(THREADS)
fused_mamba_kernel(const float* __restrict__ X,
                   const float* __restrict__ A,
                   const float* __restrict__ B,
                   float* __restrict__ out) {
    extern __shared__ float sm[];
    float* ws = sm + WS_OFF;

    __shared__ float warpsum[16];
    __shared__ int   s_start;

    const int bh   = blockIdx.x;
    const int b    = bh >> 4;
    const int h    = bh & 15;
    const int tid  = threadIdx.x;
    const int lane = tid & 31;
    const int warp = tid >> 5;
    const int lh   = tid >> 8;          // l-half group (0/1)
    const int r    = tid & 255;
    const int p0   = (r >> 4) << 2;     // 4 p-values (p0..p0+3)
    const int n0   = (r & 15) << 2;     // 4 n-values (n0..n0+3)

    const float4* X4 = (const float4*)X;
    const float4* B4 = (const float4*)B;
    const float*  Ab = A + (long)b * SDIM * HDIM + h;

    if (tid == 0) s_start = NCHUNK - 1;

    // ---- Speculative prefetch: chunks 60..63 -------------------------------
    #pragma unroll
    for (int s = 0; s < CAP; s++)
        load_chunk(sm, s, PRE0 + s, b, h, tid, X4, B4);
    asm volatile("cp.async.commit_group;" ::: "memory");

    // ---- Backward windowed A-scan (usually ONE window) ---------------------
    float suffixBeyond = 0.0f;
    int winEnd = SDIM;
    for (;;) {
        const int winStart = winEnd - WIN;
        const float a0 = Ab[(winStart + 2 * tid)     * HDIM];
        const float a1 = Ab[(winStart + 2 * tid + 1) * HDIM];
        float sc = a0 + a1;
        #pragma unroll
        for (int d = 1; d < 32; d <<= 1) {
            float o = __shfl_up_sync(0xffffffffu, sc, d);
            if (lane >= d) sc += o;
        }
        if (lane == 31) warpsum[warp] = sc;
        __syncthreads();
        if (warp == 0 && lane < 16) {
            float v = warpsum[lane];
            #pragma unroll
            for (int d = 1; d < 16; d <<= 1) {
                float o = __shfl_up_sync(0x0000ffffu, v, d);
                if (lane >= d) v += o;
            }
            warpsum[lane] = v;
        }
        __syncthreads();
        const float off   = (warp > 0) ? warpsum[warp - 1] : 0.0f;
        const float total = warpsum[15];
        const float cs1 = sc + off;
        const float cs0 = cs1 - a1;
        float2 wv;
        wv.x = __expf(total - cs0 + suffixBeyond);
        wv.y = __expf(total - cs1 + suffixBeyond);
        ((float2*)(ws + winStart))[tid] = wv;
        if (lane == 31) {                       // t1 ends a chunk
            const float Uj = total - cs1 + suffixBeyond;
            if (Uj > -THRESH) atomicMin(&s_start, (winStart + 2 * tid + 1) >> 6);
        }
        const float newSuffix = suffixBeyond + total;
        __syncthreads();
        if (winStart == 0 || newSuffix < -THRESH) break;
        suffixBeyond = newSuffix;
        winEnd = winStart;
    }
    const int start = s_start;
    __syncthreads();

    unsigned long long acc[4][2];
    #pragma unroll
    for (int i = 0; i < 4; i++) { acc[i][0] = 0ull; acc[i][1] = 0ull; }

    // ---- Prefetched chunks: scale+dup, then compute -------------------------
    asm volatile("cp.async.wait_group 0;" ::: "memory");
    __syncthreads();

    const int s0 = (start > PRE0) ? (start - PRE0) : 0;
    for (int s = s0; s < CAP; s++)
        scale_dup(sm, ws, s, PRE0 + s, tid);   // internal sync (all threads)
    __syncthreads();

    for (int s = s0; s < CAP; s++)
        compute_chunk(sm, s, lh, p0, n0, acc);

    // ---- Fallback: earlier active chunks (start<60, ~never) ----------------
    for (int c0 = start; c0 < PRE0; c0 += CAP) {
        const int nc = min(CAP, PRE0 - c0);
        __syncthreads();
        for (int c = 0; c < nc; c++)
            load_chunk(sm, c, c0 + c, b, h, tid, X4, B4);
        asm volatile("cp.async.commit_group;" ::: "memory");
        asm volatile("cp.async.wait_group 0;" ::: "memory");
        __syncthreads();
        for (int c = 0; c < nc; c++)
            scale_dup(sm, ws, c, c0 + c, tid);
        __syncthreads();
        for (int c = 0; c < nc; c++)
            compute_chunk(sm, c, lh, p0, n0, acc);
    }

    // ---- Cross-group reduction, then output (group 0) ----------------------
    __syncthreads();
    unsigned long long* buf = (unsigned long long*)sm;   // reuse xsd region
    if (lh == 1) {
        #pragma unroll
        for (int q = 0; q < 8; q++)
            buf[q * 256 + r] = acc[q >> 1][q & 1];
    }
    __syncthreads();
    if (lh == 0) {
        #pragma unroll
        for (int q = 0; q < 8; q++)
            fadd2(acc[q >> 1][q & 1], buf[q * 256 + r]);

        float4* out4 = (float4*)out + (long)bh * PDIM * 16;
        #pragma unroll
        for (int i = 0; i < 4; i++) {
            F4U2 v;
            v.u2[0] = acc[i][0];     // (n0, n0+1)
            v.u2[1] = acc[i][1];     // (n0+2, n0+3)
            out4[(p0 + i) * 16 + (n0 >> 2)] = v.f4;
        }
    }
}

// ---------------------------------------------------------------------------
extern "C" void kernel_launch(void* const* d_in, const int* in_sizes, int n_in,
                              void* d_out, int out_size) {
    const float* X = (const float*)d_in[0];
    const float* A = (const float*)d_in[1];
    const float* B = (const float*)d_in[2];
    float* out = (float*)d_out;

    cudaFuncSetAttribute(fused_mamba_kernel,
                         cudaFuncAttributeMaxDynamicSharedMemorySize,
                         SMEM_BYTES);
    fused_mamba_kernel<<<NBH, THREADS, SMEM_BYTES>>>(X, A, B, out);
}